// round 4
// baseline (speedup 1.0000x reference)
#include <cuda_runtime.h>
#include <cuda_bf16.h>
#include <cstdint>

// Problem constants
#define BB 8
#define CC 256
#define FHH 64
#define FWW 64
#define SS (FHH * FWW)          // 4096 spatial positions per batch
#define NN 131072
#define MARGIN 12.0f

#define SPW 16                  // samples per warp
#define GBLOCKS (NN / (8 * SPW))  // 1024 gather blocks (8 warps/block)

// Scratch: channels-last bf16 copies (B, S, C). 16MB each -> both fit L2.
__device__ __nv_bfloat16 g_q_b[(size_t)BB * SS * CC];
__device__ __nv_bfloat16 g_r_b[(size_t)BB * SS * CC];
// Per-position squared-norm partials for r: 4 c-tile partials per position.
__device__ float4 g_rn[(size_t)BB * SS];
__device__ float g_partials[GBLOCKS];
__device__ unsigned int g_count = 0;

// ---------------------------------------------------------------------------
// Fused transpose + downconvert + r-norm partials.
// f32 NCHW -> bf16 (B, S, C) for BOTH tensors; for r also computes per-position
// partial sum of squares over this block's 64 channels (from the bf16-rounded
// values, so the norm identity is exact w.r.t. the stored vectors).
// grid = (S/32, C/64, 2*B); z < B handles q, z >= B handles r.
// ---------------------------------------------------------------------------
__global__ void __launch_bounds__(256)
transpose_bf16_kernel(const float* __restrict__ q, const float* __restrict__ r) {
    __shared__ __nv_bfloat16 tile[32][66];   // [s_local][c_local], pad -> conflict-free
    __shared__ float npart[8][33];

    const int z = blockIdx.z;
    const bool isR = (z >= BB);
    const float* in = isR ? r : q;
    __nv_bfloat16* out = isR ? g_r_b : g_q_b;
    const int b  = z & (BB - 1);
    const int c0 = blockIdx.y * 64;
    const int s0 = blockIdx.x * 32;
    const int tx = threadIdx.x;
    const int ty = threadIdx.y;

    const float* src = in + (size_t)b * CC * SS;
    float ps = 0.0f;
#pragma unroll
    for (int j = 0; j < 8; j++) {
        int cl = ty * 8 + j;                 // channel within tile: 0..63
        __nv_bfloat16 vb = __float2bfloat16(src[(size_t)(c0 + cl) * SS + s0 + tx]);
        tile[tx][cl] = vb;
        float vf = __bfloat162float(vb);
        ps = fmaf(vf, vf, ps);
    }
    if (isR) npart[ty][tx] = ps;
    __syncthreads();

    __nv_bfloat16* dst = out + (size_t)b * SS * CC;
#pragma unroll
    for (int j = 0; j < 4; j++) {
        int sl = ty + j * 8;                 // 0..31
        __nv_bfloat162 v = *(const __nv_bfloat162*)&tile[sl][2 * tx];
        *(__nv_bfloat162*)&dst[(size_t)(s0 + sl) * CC + c0 + 2 * tx] = v;
    }

    if (isR && ty == 0) {
        float t = 0.0f;
#pragma unroll
        for (int k = 0; k < 8; k++) t += npart[k][tx];
        ((float*)g_rn)[((size_t)b * SS + s0 + tx) * 4 + blockIdx.y] = t;
    }
}

// ---------------------------------------------------------------------------
// Gather + triplet loss + full reduction.
// Each warp handles SPW=16 samples: lanes 0..15 own one sample's index
// prologue each (lanes 16..31 duplicate -> free broadcast loads); the warp
// then processes the 16 samples with 4 SHFL broadcasts + 3 coalesced uint4
// loads per sample. dp-dn = ||p||^2 - ||n||^2 - 2 a.(p-n).
// ---------------------------------------------------------------------------
__device__ __forceinline__ void dot2(unsigned int ua, unsigned int up,
                                     unsigned int un, float& dot) {
    __nv_bfloat162 d2 = __hsub2(*(const __nv_bfloat162*)&up,
                                *(const __nv_bfloat162*)&un);
    float2 df = __bfloat1622float2(d2);
    float2 af = __bfloat1622float2(*(const __nv_bfloat162*)&ua);
    dot = fmaf(af.x, df.x, dot);
    dot = fmaf(af.y, df.y, dot);
}

__global__ void __launch_bounds__(256)
gather_loss_kernel(const int* __restrict__ batch_idx,
                   const int* __restrict__ anchor_yx,
                   const int* __restrict__ pos_yx,
                   const int* __restrict__ neg_yx,
                   float* __restrict__ out) {
    const int warp = threadIdx.x >> 5;
    const int lane = threadIdx.x & 31;
    const int i = (blockIdx.x * 8 + warp) * SPW + (lane & (SPW - 1));

    // Prologue: per-lane sample index math (coalesced; upper half duplicates).
    const int b = batch_idx[i];
    const int2 ayx = ((const int2*)anchor_yx)[i];
    const int2 pyx = ((const int2*)pos_yx)[i];
    const int2 nyx = ((const int2*)neg_yx)[i];
    const int posP = b * SS + pyx.x * FWW + pyx.y;
    const int posN = b * SS + nyx.x * FWW + nyx.y;
    const int offA = (b * SS + ayx.x * FWW + ayx.y) * CC;
    const int offP = posP * CC;
    const int offN = posN * CC;
    const float4 np4 = g_rn[posP];
    const float4 nn4 = g_rn[posN];
    const float ndm = ((np4.x + np4.y) + (np4.z + np4.w))
                    - ((nn4.x + nn4.y) + (nn4.z + nn4.w)) + MARGIN;

    const int le = lane * 8;   // element offset within a 256-elem vector
    float acc = 0.0f;

#pragma unroll 8
    for (int t = 0; t < SPW; t++) {
        const int oA = __shfl_sync(0xFFFFFFFFu, offA, t);
        const int oP = __shfl_sync(0xFFFFFFFFu, offP, t);
        const int oN = __shfl_sync(0xFFFFFFFFu, offN, t);
        const float nd = __shfl_sync(0xFFFFFFFFu, ndm, t);

        const uint4 av = *(const uint4*)(g_q_b + oA + le);
        const uint4 pv = *(const uint4*)(g_r_b + oP + le);
        const uint4 nv = *(const uint4*)(g_r_b + oN + le);

        float dot = 0.0f;
        dot2(av.x, pv.x, nv.x, dot);
        dot2(av.y, pv.y, nv.y, dot);
        dot2(av.z, pv.z, nv.z, dot);
        dot2(av.w, pv.w, nv.w, dot);

#pragma unroll
        for (int off = 16; off > 0; off >>= 1)
            dot += __shfl_xor_sync(0xFFFFFFFFu, dot, off);

        acc += fmaxf(fmaf(-2.0f, dot, nd), 0.0f);   // relu(dp-dn+margin)
    }

    // acc is warp-uniform after the butterfly. Block reduce: 8 warp values.
    __shared__ float s_loss[8];
    __shared__ bool s_last;
    __shared__ float s_red[256];

    if (lane == 0) s_loss[warp] = acc;
    __syncthreads();

    if (threadIdx.x == 0) {
        float bs = 0.0f;
#pragma unroll
        for (int w = 0; w < 8; w++) bs += s_loss[w];
        g_partials[blockIdx.x] = bs;
        __threadfence();
        unsigned int c = atomicAdd(&g_count, 1u);
        s_last = (c == (unsigned int)(GBLOCKS - 1));
    }
    __syncthreads();

    // Last block to arrive reduces all partials (deterministic order).
    if (s_last) {
        volatile float* vp = g_partials;
        float t = 0.0f;
        for (int j = threadIdx.x; j < GBLOCKS; j += 256) t += vp[j];
        s_red[threadIdx.x] = t;
        __syncthreads();
#pragma unroll
        for (int st = 128; st > 0; st >>= 1) {
            if (threadIdx.x < st) s_red[threadIdx.x] += s_red[threadIdx.x + st];
            __syncthreads();
        }
        if (threadIdx.x == 0) {
            out[0] = s_red[0] / (1e-6f + (float)NN);
            g_count = 0;   // reset for next graph replay
        }
    }
}

extern "C" void kernel_launch(void* const* d_in, const int* in_sizes, int n_in,
                              void* d_out, int out_size) {
    const float* q  = (const float*)d_in[0]; // sketch_query_vectors (B,C,FH,FW)
    const float* r  = (const float*)d_in[1]; // ref_key_vectors      (B,C,FH,FW)
    const int* bidx = (const int*)d_in[2];   // batch_idx (N)
    const int* a_yx = (const int*)d_in[3];   // anchor_yx (N,2)
    const int* p_yx = (const int*)d_in[4];   // pos_yx    (N,2)
    const int* n_yx = (const int*)d_in[5];   // neg_yx    (N,2)
    float* out = (float*)d_out;

    dim3 tgrid(SS / 32, CC / 64, 2 * BB);    // (128, 4, 16)
    transpose_bf16_kernel<<<tgrid, dim3(32, 8)>>>(q, r);

    gather_loss_kernel<<<GBLOCKS, 256>>>(bidx, a_yx, p_yx, n_yx, out);
}